// round 3
// baseline (speedup 1.0000x reference)
#include <cuda_runtime.h>
#include <cfloat>

// Problem constants (from reference)
#define PB 7      // pooled bins per dim
#define HH 50
#define WW 50
#define CC 512
#define BB 2
#define RR 64
#define C4 (CC / 4)   // 128 float4 per pixel

// One CTA per (b, r, py) — a full row of 7 output bins. 256 threads:
//   c4   = tid & 127  : this thread's float4 channel slice
//   half = tid >> 7   : 0 -> bins px 0..3, 1 -> bins px 4..6
// Warp halves are whole warps (0-3 vs 4-7), so no intra-warp divergence.
//
// Facts proved from input ranges: extent in [7,26) => bin sizes sy,sx in
// [1,4]; window always fully in-bounds (max index y0+h-1 <= 48 < 50).
__device__ __forceinline__ void vmax(float4& m, float4 v) {
    m.x = fmaxf(m.x, v.x);
    m.y = fmaxf(m.y, v.y);
    m.z = fmaxf(m.z, v.z);
    m.w = fmaxf(m.w, v.w);
}

__global__ __launch_bounds__(256) void roipool_kernel(
    const float4* __restrict__ fm,    // (B,H,W,C) as float4
    const int*    __restrict__ rois,  // (B,R,4) int32: y0,x0,h,w
    float4*       __restrict__ out)   // (B,R,P,P,C) as float4
{
    int idx = blockIdx.x;             // b*R*PB + r*PB + py   (grid = 896)
    int py = idx % PB;
    int t  = idx / PB;
    int r  = t % RR;
    int b  = t / RR;

    int c4   = threadIdx.x & (C4 - 1);
    int half = threadIdx.x >> 7;
    int pxb  = half * 4;              // first px bin this thread owns

    const int4 roi = __ldg((const int4*)(rois + (b * RR + r) * 4));
    int y0 = roi.x, x0 = roi.y, h = roi.z, w = roi.w;

    // Bin bounds — fp32 arithmetic exactly as the reference:
    // step = extent/7 (fp32), start = trunc(i*step), end = trunc((i+1)*step),
    // last bin end = extent, size = max(end-start, 1).
    float stepy = (float)h / 7.0f;
    float stepx = (float)w / 7.0f;
    int ys = (int)((float)py * stepy);
    int ye = (py == PB - 1) ? h : (int)((float)(py + 1) * stepy);
    int sy = max(ye - ys, 1);         // uniform across the CTA, 1..4

    int xs[4], sx[4];
    #pragma unroll
    for (int i = 0; i < 4; ++i) {
        int px = pxb + i;
        if (px < PB) {
            int s = (int)((float)px * stepx);
            int e = (px == PB - 1) ? w : (int)((float)(px + 1) * stepx);
            xs[i] = s;
            sx[i] = max(e - s, 1);    // 1..4
        } else {
            xs[i] = 0;
            sx[i] = 0;                // dummy bin: no loads, no store
        }
    }

    // Base: top row of this bin-row's window, left edge of the RoI,
    // this thread's channel slice.
    const float4* base = fm
        + ((size_t)((b * HH + (y0 + ys)) * WW + x0)) * C4
        + c4;

    float4 m[4];
    #pragma unroll
    for (int i = 0; i < 4; ++i)
        m[i] = make_float4(-FLT_MAX, -FLT_MAX, -FLT_MAX, -FLT_MAX);

    for (int dy = 0; dy < sy; ++dy) {
        const float4* rp = base + (size_t)dy * (WW * C4);
        #pragma unroll
        for (int i = 0; i < 4; ++i) {
            #pragma unroll
            for (int dx = 0; dx < 4; ++dx) {
                if (dx < sx[i]) {
                    float4 v = __ldg(rp + (xs[i] + dx) * C4);
                    vmax(m[i], v);
                }
            }
        }
    }

    // out layout: (b, r, py, px, c4)
    size_t obase = ((size_t)(((b * RR + r) * PB + py) * PB + pxb)) * C4 + c4;
    #pragma unroll
    for (int i = 0; i < 4; ++i) {
        if (pxb + i < PB)
            out[obase + (size_t)i * C4] = m[i];
    }
}

extern "C" void kernel_launch(void* const* d_in, const int* in_sizes, int n_in,
                              void* d_out, int out_size) {
    const float4* fm   = (const float4*)d_in[0];  // x_maps float32 (2,50,50,512)
    const int*    rois = (const int*)d_in[1];     // x_rois int32 (2,64,4)
    float4*       out  = (float4*)d_out;          // (2,64,7,7,512) float32

    int nblocks = BB * RR * PB;  // 896
    roipool_kernel<<<nblocks, 256>>>(fm, rois, out);
}

// round 4
// speedup vs baseline: 1.1786x; 1.1786x over previous
#include <cuda_runtime.h>
#include <cfloat>

// Problem constants (from reference)
#define PB 7      // pooled bins per dim
#define HH 50
#define WW 50
#define CC 512
#define BB 2
#define RR 64
#define C4 (CC / 4)   // 128 float4 per pixel

// One CTA per (b, r, py, px) output bin. 128 threads, each owns one float4
// of the 512 channels.
//
// Facts proved from input ranges: extent in [7,26) => bin sizes sy,sx in
// [1,4]; window always fully in-bounds (max index y0+h-1 <= 48 < 50).
//
// (sy,sx) is uniform across the CTA, so we dispatch to one of 16 fully
// unrolled compile-time cases: exactly sy*sx independent LDG.128 with
// constant offsets (max MLP, zero predicate waste), then an fmax tree.

__device__ __forceinline__ void vmax(float4& m, float4 v) {
    m.x = fmaxf(m.x, v.x);
    m.y = fmaxf(m.y, v.y);
    m.z = fmaxf(m.z, v.z);
    m.w = fmaxf(m.w, v.w);
}

template<int SY, int SX>
__device__ __forceinline__ float4 binmax(const float4* __restrict__ p) {
    float4 v[SY * SX];
    #pragma unroll
    for (int dy = 0; dy < SY; ++dy)
        #pragma unroll
        for (int dx = 0; dx < SX; ++dx)
            v[dy * SX + dx] = __ldg(p + (dy * WW + dx) * C4);

    float4 m = v[0];
    #pragma unroll
    for (int k = 1; k < SY * SX; ++k)
        vmax(m, v[k]);
    return m;
}

__global__ __launch_bounds__(C4) void roipool_kernel(
    const float4* __restrict__ fm,    // (B,H,W,C) as float4
    const int*    __restrict__ rois,  // (B,R,4) int32: y0,x0,h,w
    float4*       __restrict__ out)   // (B,R,P,P,C) as float4
{
    int idx = blockIdx.x;                 // b*R*P*P + r*P*P + py*P + px
    int px = idx % PB;
    int t  = idx / PB;
    int py = t % PB;
    t /= PB;
    int r = t % RR;
    int b = t / RR;

    const int4 roi = __ldg((const int4*)(rois + (b * RR + r) * 4));
    int y0 = roi.x, x0 = roi.y, h = roi.z, w = roi.w;

    // Bin bounds — fp32 arithmetic exactly as the reference:
    // step = extent/7 (fp32), start = trunc(i*step), end = trunc((i+1)*step),
    // last bin end = extent, size = max(end-start, 1).
    float stepy = (float)h / 7.0f;
    float stepx = (float)w / 7.0f;
    int ys = (int)((float)py * stepy);
    int ye = (py == PB - 1) ? h : (int)((float)(py + 1) * stepy);
    int sy = max(ye - ys, 1);
    int xs = (int)((float)px * stepx);
    int xe = (px == PB - 1) ? w : (int)((float)(px + 1) * stepx);
    int sx = max(xe - xs, 1);

    int c4 = threadIdx.x;  // 0..127

    const float4* p = fm
        + ((size_t)((b * HH + (y0 + ys)) * WW + (x0 + xs))) * C4
        + c4;

    float4 m;
    int code = (sy - 1) * 4 + (sx - 1);   // uniform across CTA: no divergence
    switch (code) {
        case  0: m = binmax<1,1>(p); break;
        case  1: m = binmax<1,2>(p); break;
        case  2: m = binmax<1,3>(p); break;
        case  3: m = binmax<1,4>(p); break;
        case  4: m = binmax<2,1>(p); break;
        case  5: m = binmax<2,2>(p); break;
        case  6: m = binmax<2,3>(p); break;
        case  7: m = binmax<2,4>(p); break;
        case  8: m = binmax<3,1>(p); break;
        case  9: m = binmax<3,2>(p); break;
        case 10: m = binmax<3,3>(p); break;
        case 11: m = binmax<3,4>(p); break;
        case 12: m = binmax<4,1>(p); break;
        case 13: m = binmax<4,2>(p); break;
        case 14: m = binmax<4,3>(p); break;
        default: m = binmax<4,4>(p); break;
    }

    out[(size_t)idx * C4 + c4] = m;
}

extern "C" void kernel_launch(void* const* d_in, const int* in_sizes, int n_in,
                              void* d_out, int out_size) {
    const float4* fm   = (const float4*)d_in[0];  // x_maps float32 (2,50,50,512)
    const int*    rois = (const int*)d_in[1];     // x_rois int32 (2,64,4)
    float4*       out  = (float4*)d_out;          // (2,64,7,7,512) float32

    int nblocks = BB * RR * PB * PB;  // 6272
    roipool_kernel<<<nblocks, C4>>>(fm, rois, out);
}